// round 12
// baseline (speedup 1.0000x reference)
#include <cuda_runtime.h>
#include <math.h>

// B=8, C=128, N=8192, K=9, PAD=4, DIL=1, STR=1, L=N
#define Bv 8
#define Cv 128
#define Nv 8192
#define Kv 9
#define HALF_K 4
#define TL 128           // l positions per block tile
#define THREADS 256
#define CPB 128          // ALL channels in one block -> phase1 amortized 16x
#define NITER (CPB / 8)  // 16 channel iterations

typedef unsigned long long ull;
union F2U { float2 f; ull u; };

__device__ __forceinline__ ull pk2(float lo, float hi) {
    F2U t; t.f = make_float2(lo, hi); return t.u;
}
__device__ __forceinline__ float lo2(ull v) { F2U t; t.u = v; return t.f.x; }
__device__ __forceinline__ float hi2(ull v) { F2U t; t.u = v; return t.f.y; }
__device__ __forceinline__ ull mul2(ull a, ull b) {
    ull d; asm("mul.rn.f32x2 %0, %1, %2;" : "=l"(d) : "l"(a), "l"(b)); return d;
}
__device__ __forceinline__ ull fma2(ull a, ull b, ull c) {
    ull d; asm("fma.rn.f32x2 %0, %1, %2, %3;" : "=l"(d) : "l"(a), "l"(b), "l"(c)); return d;
}

__global__ __launch_bounds__(THREADS, 4)
void swconv_kernel(const float* __restrict__ x,
                   const float* __restrict__ coords,
                   const float* __restrict__ sigma,
                   const float* __restrict__ weight,
                   float* __restrict__ out)
{
    __shared__ float  dwT[Kv][TL];    // [k][l] transposed, 16B-aligned rows
    __shared__ float2 ws2[CPB * Kv];  // weights duplicated (w,w) -> uniform LDS.64

    const int b    = blockIdx.y;
    const int l0g  = blockIdx.x * TL;
    const int tid  = threadIdx.x;

    // ---- weights (all 128 channels), duplicated for packed math ----
    for (int i = tid; i < CPB * Kv; i += THREADS) {
        const float w = weight[i];
        ws2[i] = make_float2(w, w);
    }

    // ---- phase 1: dw[l][k], ONCE per (b, l-tile); k-halves across 256 thr ----
    {
        const int l_loc = tid & (TL - 1);
        const int khalf = tid >> 7;
        const int l     = l0g + l_loc;
        const float* cb = coords + b * 3 * Nv;
        const float cx = cb[l];
        const float cy = cb[Nv + l];
        const float cz = cb[2 * Nv + l];
        const float inv_sig = 1.0f / sigma[0];
        const int k0 = khalf ? 5 : 0;
        const int k1 = khalf ? Kv : 5;
        for (int k = k0; k < k1; k++) {
            const int idx = l + k - HALF_K;
            float dx, dy, dz;
            if (idx >= 0 && idx < Nv) {
                dx = cb[idx]          - cx;
                dy = cb[Nv + idx]     - cy;
                dz = cb[2 * Nv + idx] - cz;
            } else {
                dx = -cx; dy = -cy; dz = -cz;   // zero-padded coords
            }
            const float sq   = dx * dx + dy * dy + dz * dz;
            const float dist = (sq > 0.0f) ? sq * rsqrtf(sq) : 0.0f;  // == sqrt(sq)
            dwT[k][l_loc] = fmaxf(fmaf(-dist, inv_sig, 1.0f), 0.0f);
        }
    }
    __syncthreads();

    const int lane = tid & 31;
    const int w_id = tid >> 5;          // warp -> channel offset within pass
    const int lq   = lane * 4;          // local l of first output
    const int lg   = l0g + lq;          // global l

    // dq cache as packed pairs, read directly as ulonglong2 (zero packs)
    ull dqA[Kv], dqB[Kv];
    #pragma unroll
    for (int k = 0; k < Kv; k++) {
        const ulonglong2 dd = *reinterpret_cast<const ulonglong2*>(&dwT[k][lq]);
        dqA[k] = dd.x;                  // (dw[l], dw[l+1])
        dqB[k] = dd.y;                  // (dw[l+2], dw[l+3])
    }

    const bool interior = (l0g >= HALF_K) && (l0g + TL + HALF_K <= Nv);

    if (interior) {
        const float* xb0 = x   + (b * Cv + w_id) * Nv + lg;  // iter stride 8*Nv
        float*       ob0 = out + (b * Cv + w_id) * Nv + lg;

        #pragma unroll 4
        for (int it = 0; it < NITER; ++it) {
            const float* xp = xb0 + it * 8 * Nv;
            // even pairs free via 128-bit loads
            const ulonglong2 A = *reinterpret_cast<const ulonglong2*>(xp - 4);
            const ulonglong2 M = *reinterpret_cast<const ulonglong2*>(xp);
            const ulonglong2 R = *reinterpret_cast<const ulonglong2*>(xp + 4);
            const ull P0 = A.x, P1 = A.y, P2 = M.x, P3 = M.y, P4 = R.x, P5 = R.y;
            // odd-shifted pairs (only 5 packs per iter)
            const ull q0 = pk2(hi2(P0), lo2(P1));
            const ull q1 = pk2(hi2(P1), lo2(P2));
            const ull q2 = pk2(hi2(P2), lo2(P3));
            const ull q3 = pk2(hi2(P3), lo2(P4));
            const ull q4 = pk2(hi2(P4), lo2(P5));
            const ull xA[Kv] = { P0, q0, P1, q1, P2, q2, P3, q3, P4 };
            const ull xB[Kv] = { P1, q1, P2, q2, P3, q3, P4, q4, P5 };

            const ull* wc2 = reinterpret_cast<const ull*>(&ws2[(it * 8 + w_id) * Kv]);
            ull accA = 0ull, accB = 0ull;
            #pragma unroll
            for (int k = 0; k < Kv; k++) {
                const ull w2 = wc2[k];          // warp-uniform LDS.64
                accA = fma2(mul2(xA[k], dqA[k]), w2, accA);
                accB = fma2(mul2(xB[k], dqB[k]), w2, accB);
            }
            F2U ra, rb; ra.u = accA; rb.u = accB;
            *reinterpret_cast<float4*>(ob0 + it * 8 * Nv) =
                make_float4(ra.f.x, ra.f.y, rb.f.x, rb.f.y);
        }
    } else {
        // boundary tiles (2 of 64 in l): guarded path
        #pragma unroll 4
        for (int it = 0; it < NITER; ++it) {
            const int c = it * 8 + w_id;
            const float* xb = x + (b * Cv + c) * Nv;
            float xv[12];
            #pragma unroll
            for (int j = 0; j < 12; j++) {
                const int idx = lg - HALF_K + j;
                xv[j] = (idx >= 0 && idx < Nv) ? xb[idx] : 0.0f;
            }
            const ull* wc2 = reinterpret_cast<const ull*>(&ws2[c * Kv]);
            ull accA = 0ull, accB = 0ull;
            #pragma unroll
            for (int k = 0; k < Kv; k++) {
                const ull w2 = wc2[k];
                accA = fma2(mul2(pk2(xv[k],     xv[k + 1]), dqA[k]), w2, accA);
                accB = fma2(mul2(pk2(xv[k + 2], xv[k + 3]), dqB[k]), w2, accB);
            }
            F2U ra, rb; ra.u = accA; rb.u = accB;
            *reinterpret_cast<float4*>(out + (b * Cv + c) * Nv + lg) =
                make_float4(ra.f.x, ra.f.y, rb.f.x, rb.f.y);
        }
    }
}

extern "C" void kernel_launch(void* const* d_in, const int* in_sizes, int n_in,
                              void* d_out, int out_size)
{
    const float* x      = (const float*)d_in[0];
    const float* coords = (const float*)d_in[1];
    const float* sigma  = (const float*)d_in[2];
    const float* weight = (const float*)d_in[3];
    float* out = (float*)d_out;

    dim3 grid(Nv / TL, Bv, 1);   // (64, 8, 1) = 512 blocks, one clean wave
    swconv_kernel<<<grid, THREADS>>>(x, coords, sigma, weight, out);
}

// round 13
// speedup vs baseline: 1.1241x; 1.1241x over previous
#include <cuda_runtime.h>
#include <math.h>

// B=8, C=128, N=8192, K=9, PAD=4, DIL=1, STR=1, L=N
#define Bv 8
#define Cv 128
#define Nv 8192
#define Kv 9
#define HALF_K 4
#define TL 128           // l positions per block tile
#define THREADS 256
#define CPB 32           // channels per block (R10 config: 2048 blocks)
#define NITER (CPB / 8)  // 4 channel iterations

typedef unsigned long long ull;
union F2U { float2 f; ull u; };

__device__ __forceinline__ ull pk2(float lo, float hi) {
    F2U t; t.f = make_float2(lo, hi); return t.u;
}
__device__ __forceinline__ float lo2(ull v) { F2U t; t.u = v; return t.f.x; }
__device__ __forceinline__ float hi2(ull v) { F2U t; t.u = v; return t.f.y; }
__device__ __forceinline__ ull mul2(ull a, ull b) {
    ull d; asm("mul.rn.f32x2 %0, %1, %2;" : "=l"(d) : "l"(a), "l"(b)); return d;
}
__device__ __forceinline__ ull fma2(ull a, ull b, ull c) {
    ull d; asm("fma.rn.f32x2 %0, %1, %2, %3;" : "=l"(d) : "l"(a), "l"(b), "l"(c)); return d;
}

__global__ __launch_bounds__(THREADS, 4)
void swconv_kernel(const float* __restrict__ x,
                   const float* __restrict__ coords,
                   const float* __restrict__ sigma,
                   const float* __restrict__ weight,
                   float* __restrict__ out)
{
    __shared__ float  dwT[Kv][TL];    // [k][l] transposed, 16B-aligned rows
    __shared__ float2 ws2[CPB * Kv];  // weights duplicated (w,w) -> uniform LDS.64

    const int b     = blockIdx.y;
    const int l0g   = blockIdx.x * TL;
    const int cbase = blockIdx.z * CPB;
    const int tid   = threadIdx.x;

    // ---- weights slice, duplicated for packed math ----
    for (int i = tid; i < CPB * Kv; i += THREADS) {
        const float w = weight[cbase * Kv + i];
        ws2[i] = make_float2(w, w);
    }

    // ---- phase 1: dw[l][k], k-halves across 256 threads ----
    {
        const int l_loc = tid & (TL - 1);
        const int khalf = tid >> 7;
        const int l     = l0g + l_loc;
        const float* cb = coords + b * 3 * Nv;
        const float cx = cb[l];
        const float cy = cb[Nv + l];
        const float cz = cb[2 * Nv + l];
        const float inv_sig = 1.0f / sigma[0];
        const int k0 = khalf ? 5 : 0;
        const int k1 = khalf ? Kv : 5;
        for (int k = k0; k < k1; k++) {
            const int idx = l + k - HALF_K;
            float dx, dy, dz;
            if (idx >= 0 && idx < Nv) {
                dx = cb[idx]          - cx;
                dy = cb[Nv + idx]     - cy;
                dz = cb[2 * Nv + idx] - cz;
            } else {
                dx = -cx; dy = -cy; dz = -cz;   // zero-padded coords
            }
            const float sq   = dx * dx + dy * dy + dz * dz;
            const float dist = (sq > 0.0f) ? sq * rsqrtf(sq) : 0.0f;  // == sqrt(sq)
            dwT[k][l_loc] = fmaxf(fmaf(-dist, inv_sig, 1.0f), 0.0f);
        }
    }
    __syncthreads();

    const int lane = tid & 31;
    const int w_id = tid >> 5;          // warp -> channel offset within pass
    const int lq   = lane * 4;          // local l of first output
    const int lg   = l0g + lq;          // global l

    // dq cache as packed pairs, read directly as ulonglong2 (zero packs)
    ull dqA[Kv], dqB[Kv];
    #pragma unroll
    for (int k = 0; k < Kv; k++) {
        const ulonglong2 dd = *reinterpret_cast<const ulonglong2*>(&dwT[k][lq]);
        dqA[k] = dd.x;                  // (dw[l], dw[l+1])
        dqB[k] = dd.y;                  // (dw[l+2], dw[l+3])
    }

    const bool interior = (l0g >= HALF_K) && (l0g + TL + HALF_K <= Nv);

    if (interior) {
        const float* xb0 = x   + (b * Cv + cbase + w_id) * Nv + lg;  // stride 8*Nv
        float*       ob0 = out + (b * Cv + cbase + w_id) * Nv + lg;

        #pragma unroll
        for (int it = 0; it < NITER; ++it) {
            const float* xp = xb0 + it * 8 * Nv;
            // even pairs free via 128-bit loads
            const ulonglong2 A = *reinterpret_cast<const ulonglong2*>(xp - 4);
            const ulonglong2 M = *reinterpret_cast<const ulonglong2*>(xp);
            const ulonglong2 R = *reinterpret_cast<const ulonglong2*>(xp + 4);
            const ull P0 = A.x, P1 = A.y, P2 = M.x, P3 = M.y, P4 = R.x, P5 = R.y;
            // odd-shifted pairs (only 5 packs per iter)
            const ull q0 = pk2(hi2(P0), lo2(P1));
            const ull q1 = pk2(hi2(P1), lo2(P2));
            const ull q2 = pk2(hi2(P2), lo2(P3));
            const ull q3 = pk2(hi2(P3), lo2(P4));
            const ull q4 = pk2(hi2(P4), lo2(P5));
            const ull xA[Kv] = { P0, q0, P1, q1, P2, q2, P3, q3, P4 };
            const ull xB[Kv] = { P1, q1, P2, q2, P3, q3, P4, q4, P5 };

            const ull* wc2 = reinterpret_cast<const ull*>(&ws2[(it * 8 + w_id) * Kv]);
            ull accA = 0ull, accB = 0ull;
            #pragma unroll
            for (int k = 0; k < Kv; k++) {
                const ull w2 = wc2[k];          // warp-uniform LDS.64
                accA = fma2(mul2(xA[k], dqA[k]), w2, accA);
                accB = fma2(mul2(xB[k], dqB[k]), w2, accB);
            }
            F2U ra, rb; ra.u = accA; rb.u = accB;
            *reinterpret_cast<float4*>(ob0 + it * 8 * Nv) =
                make_float4(ra.f.x, ra.f.y, rb.f.x, rb.f.y);
        }
    } else {
        // boundary tiles (2 of 64 in l): guarded path
        #pragma unroll
        for (int it = 0; it < NITER; ++it) {
            const int c = cbase + it * 8 + w_id;
            const float* xb = x + (b * Cv + c) * Nv;
            float xv[12];
            #pragma unroll
            for (int j = 0; j < 12; j++) {
                const int idx = lg - HALF_K + j;
                xv[j] = (idx >= 0 && idx < Nv) ? xb[idx] : 0.0f;
            }
            const ull* wc2 = reinterpret_cast<const ull*>(&ws2[c * Kv - cbase * Kv]);
            ull accA = 0ull, accB = 0ull;
            #pragma unroll
            for (int k = 0; k < Kv; k++) {
                const ull w2 = wc2[k];
                accA = fma2(mul2(pk2(xv[k],     xv[k + 1]), dqA[k]), w2, accA);
                accB = fma2(mul2(pk2(xv[k + 2], xv[k + 3]), dqB[k]), w2, accB);
            }
            F2U ra, rb; ra.u = accA; rb.u = accB;
            *reinterpret_cast<float4*>(out + (b * Cv + c) * Nv + lg) =
                make_float4(ra.f.x, ra.f.y, rb.f.x, rb.f.y);
        }
    }
}

extern "C" void kernel_launch(void* const* d_in, const int* in_sizes, int n_in,
                              void* d_out, int out_size)
{
    const float* x      = (const float*)d_in[0];
    const float* coords = (const float*)d_in[1];
    const float* sigma  = (const float*)d_in[2];
    const float* weight = (const float*)d_in[3];
    float* out = (float*)d_out;

    dim3 grid(Nv / TL, Bv, Cv / CPB);   // (64, 8, 4) = 2048 blocks
    swconv_kernel<<<grid, THREADS>>>(x, coords, sigma, weight, out);
}